// round 12
// baseline (speedup 1.0000x reference)
#include <cuda_runtime.h>
#include <cuda_fp16.h>
#include <cstdint>

#define D_IN_    128
#define D_HID_   256
#define TILE_M   64
#define NTHREADS 512

// ---- SMEM byte layout (row stride 256B = 128 fp16; 16B-chunk XOR swizzle) ----
#define A0_OFF     0         // A double buffer: 2 x (64 x 128 fp16 = 16 KB)
#define A_BUF_SZ   16384
#define W_OFF      32768     // W1 staging: 256 x 128 fp16 = 64 KB
#define BW_OFF     98304     // float2[256] {b1, w2} = 2 KB
#define PART_OFF   100352    // 2 x float[64][8] = 4 KB
#define SMEM_TOTAL 104448

__device__ int g_edge_is_i64;

__global__ void detect_edge_dtype(const unsigned int* __restrict__ ew) {
    if (threadIdx.x == 0 && blockIdx.x == 0) {
        int is64 = 1;
        for (int i = 0; i < 256; i++)
            if (ew[2 * i + 1] != 0u) { is64 = 0; break; }
        g_edge_is_i64 = is64;
    }
}

__device__ __forceinline__ uint32_t smem_to_u32(const void* p) {
    uint32_t a;
    asm("{ .reg .u64 t; cvta.to.shared.u64 t, %1; cvt.u32.u64 %0, t; }" : "=r"(a) : "l"(p));
    return a;
}

#define LDSM_X4(r, addr) \
    asm volatile("ldmatrix.sync.aligned.m8n8.x4.shared.b16 {%0,%1,%2,%3}, [%4];" \
        : "=r"((r)[0]), "=r"((r)[1]), "=r"((r)[2]), "=r"((r)[3]) : "r"(addr))
#define MMA16816(c, a0, a1, a2, a3, b0, b1) \
    asm volatile("mma.sync.aligned.m16n8k16.row.col.f32.f16.f16.f32 " \
        "{%0,%1,%2,%3}, {%4,%5,%6,%7}, {%8,%9}, {%0,%1,%2,%3};" \
        : "+f"((c)[0]), "+f"((c)[1]), "+f"((c)[2]), "+f"((c)[3]) \
        : "r"(a0), "r"(a1), "r"(a2), "r"(a3), "r"(b0), "r"(b1))

__device__ __forceinline__ uint32_t pack2(float x, float y) {
    __half hx = __float2half_rn(x), hy = __float2half_rn(y);
    return ((uint32_t)__half_as_ushort(hy) << 16) | (uint32_t)__half_as_ushort(hx);
}

// gather 64 edges -> A buffer at dst (coalesced: 8 threads/edge, 512 thr = 64 edges)
__device__ __forceinline__ void gather_tile(char* smem, const float* __restrict__ z,
                                            const long long* __restrict__ e64,
                                            const int* __restrict__ e32, int is64,
                                            int e_base, int n_edges,
                                            int gm, int sub, uint32_t dst)
{
    const int e = e_base + gm;
    const uint32_t rb = (uint32_t)gm * 256;
    const uint32_t swhalf = (uint32_t)(sub & 1) * 8;
    if (e < n_edges) {
        long long i0, i1;
        if (is64) { i0 = e64[e]; i1 = e64[n_edges + e]; }
        else      { i0 = e32[e]; i1 = e32[n_edges + e]; }
        const float4* z0 = reinterpret_cast<const float4*>(z) + i0 * 32 + sub;
        const float4* z1 = reinterpret_cast<const float4*>(z) + i1 * 32 + sub;
        #pragma unroll
        for (int c = 0; c < 4; c++) {
            float4 a = z0[c * 8], b = z1[c * 8];
            uint2 st;
            st.x = pack2(a.x * b.x, a.y * b.y);
            st.y = pack2(a.z * b.z, a.w * b.w);
            uint32_t kb16 = (uint32_t)(c * 64 + (sub >> 1) * 16);
            uint32_t sw = rb + (kb16 ^ (((uint32_t)gm & 7) << 4)) + swhalf;
            *reinterpret_cast<uint2*>(smem + dst + sw) = st;
        }
    } else {
        uint2 zz = {0, 0};
        #pragma unroll
        for (int c = 0; c < 4; c++) {
            uint32_t kb16 = (uint32_t)(c * 64 + (sub >> 1) * 16);
            uint32_t sw = rb + (kb16 ^ (((uint32_t)gm & 7) << 4)) + swhalf;
            *reinterpret_cast<uint2*>(smem + dst + sw) = zz;
        }
    }
}

__global__ void __launch_bounds__(NTHREADS, 1)
edge_decoder_hmma(const float* __restrict__ z,
                  const void* __restrict__ edge_raw,
                  const float* __restrict__ W1,
                  const float* __restrict__ b1,
                  const float* __restrict__ W2,
                  const float* __restrict__ b2,
                  float* __restrict__ out,
                  int n_edges)
{
    extern __shared__ char smem[];
    const uint32_t sbase = smem_to_u32(smem);
    const int tid  = threadIdx.x;
    const int wid  = tid >> 5;
    const int lane = tid & 31;
    const int wm = (wid >> 3) * 32;      // 2 m-warps x 32 rows
    const int wn = (wid & 7) * 32;       // 8 n-warps x 32 cols

    const int is64 = g_edge_is_i64;
    const long long* e64 = (const long long*)edge_raw;
    const int*       e32 = (const int*)edge_raw;

    float2* bw2s = (float2*)(smem + BW_OFF);

    // ---- prologue: W1 [256][128] -> fp16 SMEM, swizzled ----
    for (int c = tid; c < D_HID_ * 16; c += NTHREADS) {
        int n = c >> 4, ch = c & 15;
        const float4* wr = reinterpret_cast<const float4*>(W1) + n * 32 + ch * 2;
        float4 v0 = wr[0], v1 = wr[1];
        uint4 hi;
        hi.x = pack2(v0.x, v0.y); hi.y = pack2(v0.z, v0.w);
        hi.z = pack2(v1.x, v1.y); hi.w = pack2(v1.z, v1.w);
        uint32_t kb = (uint32_t)ch * 16;
        uint32_t sw = (uint32_t)n * 256 + (kb ^ (((uint32_t)n & 7) << 4));
        *reinterpret_cast<uint4*>(smem + W_OFF + sw) = hi;
    }
    if (tid < D_HID_) { float2 t; t.x = b1[tid]; t.y = W2[tid]; bw2s[tid] = t; }
    const float bias2 = b2[0];
    __syncthreads();

    // ---- load this warp's B slice (32 cols x 128 k) into registers: 64 regs ----
    uint32_t Breg[8][2][4];
    {
        const int brow0 = wn + ((lane >> 4) << 3) + (lane & 7);
        const int bksel = (lane >> 3) & 1;
        #pragma unroll
        for (int k16 = 0; k16 < 8; k16++) {
            uint32_t bkb = (uint32_t)(k16 * 32 + bksel * 16);
            #pragma unroll
            for (int n16 = 0; n16 < 2; n16++) {
                int r = brow0 + n16 * 16;
                uint32_t bd = sbase + W_OFF + (uint32_t)r * 256
                            + (bkb ^ (((uint32_t)r & 7) << 4));
                LDSM_X4(Breg[k16][n16], bd);
            }
        }
    }

    const int n_tiles = (n_edges + TILE_M - 1) / TILE_M;
    const int grid = gridDim.x;
    const int bid = blockIdx.x;

    const int sub = tid & 7;
    const int gm  = tid >> 3;    // 0..63

    // ---- gather tile 0 -> A[0] ----
    if (bid < n_tiles)
        gather_tile(smem, z, e64, e32, is64, bid * TILE_M, n_edges, gm, sub, A0_OFF);
    __syncthreads();

    int i = 0;
    for (int tile = bid; tile < n_tiles; tile += grid, i++) {
        const int abuf = i & 1;
        const uint32_t aoff = A0_OFF + (uint32_t)abuf * A_BUF_SZ;
        const int e_base = tile * TILE_M;
        float* part = (float*)(smem + PART_OFF + abuf * 2048);   // [64][8]

        // ---- HMMA: warp tile 32(m) x 32(n), K=128, B from registers ----
        float C[2][4][4];
        #pragma unroll
        for (int mb = 0; mb < 2; mb++)
            #pragma unroll
            for (int n8 = 0; n8 < 4; n8++)
                #pragma unroll
                for (int q = 0; q < 4; q++) C[mb][n8][q] = 0.0f;
        {
            const int arow = wm + (lane & 15);
            const uint32_t abase = sbase + aoff + (uint32_t)arow * 256;
            const uint32_t asw = ((uint32_t)arow & 7) << 4;
            #pragma unroll
            for (int k16 = 0; k16 < 8; k16++) {
                uint32_t Ahi[2][4];
                uint32_t akb = (uint32_t)(k16 * 32 + (lane >> 4) * 16);
                uint32_t ad = abase + (akb ^ asw);
                LDSM_X4(Ahi[0], ad);
                LDSM_X4(Ahi[1], ad + 16 * 256);
                #pragma unroll
                for (int n16 = 0; n16 < 2; n16++)
                    #pragma unroll
                    for (int j = 0; j < 2; j++) {
                        MMA16816(C[0][n16 * 2 + j], Ahi[0][0], Ahi[0][1], Ahi[0][2], Ahi[0][3],
                                 Breg[k16][n16][2 * j], Breg[k16][n16][2 * j + 1]);
                        MMA16816(C[1][n16 * 2 + j], Ahi[1][0], Ahi[1][1], Ahi[1][2], Ahi[1][3],
                                 Breg[k16][n16][2 * j], Breg[k16][n16][2 * j + 1]);
                    }
            }
        }

        // ---- gather tile i+1 -> A[abuf^1]; LDG latency hides under epilogue ----
        {
            const int ntile = tile + grid;
            if (ntile < n_tiles)
                gather_tile(smem, z, e64, e32, is64, ntile * TILE_M, n_edges,
                            gm, sub, A0_OFF + (uint32_t)(abuf ^ 1) * A_BUF_SZ);
        }

        // ---- epilogue: mish (pairwise rcp) + W2-weighted reduce ----
        {
            float psum[4] = {0.f, 0.f, 0.f, 0.f};
            #pragma unroll
            for (int n8 = 0; n8 < 4; n8++) {
                const int n = wn + n8 * 8 + 2 * (lane & 3);
                float2 bw0 = bw2s[n];
                float2 bw1 = bw2s[n + 1];
                #pragma unroll
                for (int mb = 0; mb < 2; mb++) {
                    const float* c = C[mb][n8];
                    #pragma unroll
                    for (int h = 0; h < 2; h++) {
                        float y0 = c[2 * h]     + bw0.x;
                        float y1 = c[2 * h + 1] + bw1.x;
                        float ev0 = __expf(fminf(y0, 15.0f));
                        float ev1 = __expf(fminf(y1, 15.0f));
                        float p0 = 1.0f + ev0, p1 = 1.0f + ev1;
                        float p20 = p0 * p0,   p21 = p1 * p1;
                        float n0 = p20 - 1.0f, d0 = p20 + 1.0f;
                        float n1 = p21 - 1.0f, d1 = p21 + 1.0f;
                        float r = __fdividef(1.0f, d0 * d1);
                        float m0 = y0 * n0 * (d1 * r);
                        float m1 = y1 * n1 * (d0 * r);
                        psum[mb * 2 + h] = fmaf(bw0.y, m0, fmaf(bw1.y, m1, psum[mb * 2 + h]));
                    }
                }
            }
            #pragma unroll
            for (int q = 0; q < 4; q++) {
                psum[q] += __shfl_xor_sync(0xffffffffu, psum[q], 1);
                psum[q] += __shfl_xor_sync(0xffffffffu, psum[q], 2);
            }
            if ((lane & 3) == 0) {
                const int r = lane >> 2;    // 0..7
                const int wcol = wid & 7;   // n-warp index
                #pragma unroll
                for (int mb = 0; mb < 2; mb++) {
                    part[(wm + mb * 16 + r) * 8 + wcol]       = psum[mb * 2 + 0];
                    part[(wm + mb * 16 + r + 8) * 8 + wcol]   = psum[mb * 2 + 1];
                }
            }
        }
        __syncthreads();   // part + next A ready

        if (tid < TILE_M) {
            const int e = e_base + tid;
            if (e < n_edges) {
                const float4* pr = reinterpret_cast<const float4*>(part + tid * 8);
                float4 p0 = pr[0], p1 = pr[1];
                float s = ((p0.x + p0.y) + (p0.z + p0.w))
                        + ((p1.x + p1.y) + (p1.z + p1.w)) + bias2;
                out[e] = __fdividef(1.0f, 1.0f + __expf(-s));
            }
        }
    }
}

extern "C" void kernel_launch(void* const* d_in, const int* in_sizes, int n_in,
                              void* d_out, int out_size) {
    const float* zp  = (const float*)d_in[0];
    const void*  ep  = d_in[1];
    const float* W1p = (const float*)d_in[2];
    const float* b1p = (const float*)d_in[3];
    const float* W2p = (const float*)d_in[4];
    const float* b2p = (const float*)d_in[5];
    float* outp = (float*)d_out;
    const int n_edges = out_size;

    cudaFuncSetAttribute(edge_decoder_hmma,
                         cudaFuncAttributeMaxDynamicSharedMemorySize, SMEM_TOTAL);
    int sms = 148;
    cudaDeviceGetAttribute(&sms, cudaDevAttrMultiProcessorCount, 0);

    detect_edge_dtype<<<1, 32>>>((const unsigned int*)ep);
    edge_decoder_hmma<<<sms, NTHREADS, SMEM_TOTAL>>>(
        zp, ep, W1p, b1p, W2p, b2p, outp, n_edges);
}

// round 14
// speedup vs baseline: 1.2330x; 1.2330x over previous
#include <cuda_runtime.h>
#include <cuda_fp16.h>
#include <cstdint>

#define D_IN_    128
#define D_HID_   256
#define TILE_M   32          // edges per GROUP tile
#define NTHREADS 256         // 2 groups x 4 warps

// ---- SMEM byte layout per CTA ----
// A(g,b) = g*16384 + b*8192   (32 edges x 256B, double buffered, per group)
#define W_OFF      32768     // 256 x 128 fp16 = 64 KB (shared, read-only)
#define BW_OFF     98304     // float2[256] {b1, w2} = 2 KB
#define PART_OFF   100352    // per (g,b): +(g*2+b)*512 ; float[32][4]
#define SMEM_TOTAL 102400

__device__ int g_edge_is_i64;

__global__ void detect_edge_dtype(const unsigned int* __restrict__ ew) {
    if (threadIdx.x == 0 && blockIdx.x == 0) {
        int is64 = 1;
        for (int i = 0; i < 256; i++)
            if (ew[2 * i + 1] != 0u) { is64 = 0; break; }
        g_edge_is_i64 = is64;
    }
}

__device__ __forceinline__ uint32_t smem_to_u32(const void* p) {
    uint32_t a;
    asm("{ .reg .u64 t; cvta.to.shared.u64 t, %1; cvt.u32.u64 %0, t; }" : "=r"(a) : "l"(p));
    return a;
}

#define LDSM_X4(r, addr) \
    asm volatile("ldmatrix.sync.aligned.m8n8.x4.shared.b16 {%0,%1,%2,%3}, [%4];" \
        : "=r"((r)[0]), "=r"((r)[1]), "=r"((r)[2]), "=r"((r)[3]) : "r"(addr))
#define MMA16816(c, a0, a1, a2, a3, b0, b1) \
    asm volatile("mma.sync.aligned.m16n8k16.row.col.f32.f16.f16.f32 " \
        "{%0,%1,%2,%3}, {%4,%5,%6,%7}, {%8,%9}, {%0,%1,%2,%3};" \
        : "+f"((c)[0]), "+f"((c)[1]), "+f"((c)[2]), "+f"((c)[3]) \
        : "r"(a0), "r"(a1), "r"(a2), "r"(a3), "r"(b0), "r"(b1))
#define GROUP_BAR(id) \
    asm volatile("bar.sync %0, 128;" :: "r"(id) : "memory")

__device__ __forceinline__ uint32_t pack2(float x, float y) {
    __half hx = __float2half_rn(x), hy = __float2half_rn(y);
    return ((uint32_t)__half_as_ushort(hy) << 16) | (uint32_t)__half_as_ushort(hx);
}

// gather 32 edges -> A buffer at dst; 128 group threads, 8 thr/edge, 2 passes
__device__ __forceinline__ void gather_tile(char* smem, const float* __restrict__ z,
                                            const long long* __restrict__ e64,
                                            const int* __restrict__ e32, int is64,
                                            int e_base, int n_edges,
                                            int gtid, uint32_t dst)
{
    const int sub = gtid & 7;
    const uint32_t swhalf = (uint32_t)(sub & 1) * 8;
    #pragma unroll
    for (int p = 0; p < 2; p++) {
        const int m = (gtid >> 3) + p * 16;      // 0..31
        const int e = e_base + m;
        const uint32_t rb = (uint32_t)m * 256;
        if (e < n_edges) {
            long long i0, i1;
            if (is64) { i0 = e64[e]; i1 = e64[n_edges + e]; }
            else      { i0 = e32[e]; i1 = e32[n_edges + e]; }
            const float4* z0 = reinterpret_cast<const float4*>(z) + i0 * 32 + sub;
            const float4* z1 = reinterpret_cast<const float4*>(z) + i1 * 32 + sub;
            #pragma unroll
            for (int c = 0; c < 4; c++) {
                float4 a = z0[c * 8], b = z1[c * 8];
                uint2 st;
                st.x = pack2(a.x * b.x, a.y * b.y);
                st.y = pack2(a.z * b.z, a.w * b.w);
                uint32_t kb16 = (uint32_t)(c * 64 + (sub >> 1) * 16);
                uint32_t sw = rb + (kb16 ^ (((uint32_t)m & 7) << 4)) + swhalf;
                *reinterpret_cast<uint2*>(smem + dst + sw) = st;
            }
        } else {
            uint2 zz = {0, 0};
            #pragma unroll
            for (int c = 0; c < 4; c++) {
                uint32_t kb16 = (uint32_t)(c * 64 + (sub >> 1) * 16);
                uint32_t sw = rb + (kb16 ^ (((uint32_t)m & 7) << 4)) + swhalf;
                *reinterpret_cast<uint2*>(smem + dst + sw) = zz;
            }
        }
    }
}

__global__ void __launch_bounds__(NTHREADS, 2)
edge_decoder_hmma(const float* __restrict__ z,
                  const void* __restrict__ edge_raw,
                  const float* __restrict__ W1,
                  const float* __restrict__ b1,
                  const float* __restrict__ W2,
                  const float* __restrict__ b2,
                  float* __restrict__ out,
                  int n_edges)
{
    extern __shared__ char smem[];
    const uint32_t sbase = smem_to_u32(smem);
    const int tid  = threadIdx.x;
    const int lane = tid & 31;
    const int grp  = tid >> 7;           // group 0/1 (4 warps each)
    const int gtid = tid & 127;          // thread within group
    const int wg   = (tid >> 5) & 3;     // warp within group (n-warp index)
    const int wn   = wg * 64;            // warp n-base
    const int barid = 1 + grp;           // named barrier id per group

    const int is64 = g_edge_is_i64;
    const long long* e64 = (const long long*)edge_raw;
    const int*       e32 = (const int*)edge_raw;

    float2* bw2s = (float2*)(smem + BW_OFF);

    // ---- prologue (whole CTA): W1 [256][128] -> fp16 SMEM, swizzled ----
    for (int c = tid; c < D_HID_ * 16; c += NTHREADS) {
        int n = c >> 4, ch = c & 15;
        const float4* wr = reinterpret_cast<const float4*>(W1) + n * 32 + ch * 2;
        float4 v0 = wr[0], v1 = wr[1];
        uint4 hi;
        hi.x = pack2(v0.x, v0.y); hi.y = pack2(v0.z, v0.w);
        hi.z = pack2(v1.x, v1.y); hi.w = pack2(v1.z, v1.w);
        uint32_t kb = (uint32_t)ch * 16;
        uint32_t sw = (uint32_t)n * 256 + (kb ^ (((uint32_t)n & 7) << 4));
        *reinterpret_cast<uint4*>(smem + W_OFF + sw) = hi;
    }
    if (tid < D_HID_) { float2 t; t.x = b1[tid]; t.y = W2[tid]; bw2s[tid] = t; }
    const float bias2 = b2[0];
    __syncthreads();

    // ---- per-group independent tile stream ----
    const int n_tiles = (n_edges + TILE_M - 1) / TILE_M;
    const int stride  = gridDim.x * 2;
    const int sid     = blockIdx.x * 2 + grp;

    // gather tile 0 -> A(grp, 0)
    if (sid < n_tiles)
        gather_tile(smem, z, e64, e32, is64, sid * TILE_M, n_edges,
                    gtid, (uint32_t)grp * 16384u);
    GROUP_BAR(barid);

    int i = 0;
    for (int tile = sid; tile < n_tiles; tile += stride, i++) {
        const int abuf = i & 1;
        const uint32_t aoff = (uint32_t)grp * 16384u + (uint32_t)abuf * 8192u;
        const int e_base = tile * TILE_M;
        float* part = (float*)(smem + PART_OFF + (grp * 2 + abuf) * 512);  // [32][4]

        // ---- HMMA: warp tile 32(m) x 64(n), K=128 ----
        float C[2][8][4];
        #pragma unroll
        for (int mb = 0; mb < 2; mb++)
            #pragma unroll
            for (int n8 = 0; n8 < 8; n8++)
                #pragma unroll
                for (int q = 0; q < 4; q++) C[mb][n8][q] = 0.0f;
        {
            const int arow = lane & 15;
            const uint32_t abase = sbase + aoff + (uint32_t)arow * 256;
            const uint32_t asw = ((uint32_t)arow & 7) << 4;
            const int brow = wn + ((lane >> 4) << 3) + (lane & 7);
            const int bksel = (lane >> 3) & 1;
            const uint32_t bbase = sbase + W_OFF + (uint32_t)brow * 256;
            const uint32_t bsw = ((uint32_t)brow & 7) << 4;
            #pragma unroll
            for (int k16 = 0; k16 < 8; k16++) {
                uint32_t Ahi[2][4];
                uint32_t akb = (uint32_t)(k16 * 32 + (lane >> 4) * 16);
                uint32_t ad = abase + (akb ^ asw);
                LDSM_X4(Ahi[0], ad);
                LDSM_X4(Ahi[1], ad + 16 * 256);

                uint32_t bkb = (uint32_t)(k16 * 32 + bksel * 16);
                uint32_t bd = bbase + (bkb ^ bsw);
                #pragma unroll
                for (int n16 = 0; n16 < 4; n16++) {
                    uint32_t B4[4];
                    LDSM_X4(B4, bd + (uint32_t)n16 * 4096);
                    MMA16816(C[0][2 * n16],     Ahi[0][0], Ahi[0][1], Ahi[0][2], Ahi[0][3], B4[0], B4[1]);
                    MMA16816(C[1][2 * n16],     Ahi[1][0], Ahi[1][1], Ahi[1][2], Ahi[1][3], B4[0], B4[1]);
                    MMA16816(C[0][2 * n16 + 1], Ahi[0][0], Ahi[0][1], Ahi[0][2], Ahi[0][3], B4[2], B4[3]);
                    MMA16816(C[1][2 * n16 + 1], Ahi[1][0], Ahi[1][1], Ahi[1][2], Ahi[1][3], B4[2], B4[3]);
                }
            }
        }

        // ---- gather tile i+1 -> A(grp, abuf^1); LDG latency hides under epilogue ----
        {
            const int ntile = tile + stride;
            if (ntile < n_tiles)
                gather_tile(smem, z, e64, e32, is64, ntile * TILE_M, n_edges,
                            gtid, (uint32_t)grp * 16384u + (uint32_t)(abuf ^ 1) * 8192u);
        }

        // ---- epilogue: mish (pairwise rcp) + W2-weighted reduce ----
        {
            float psum[4] = {0.f, 0.f, 0.f, 0.f};
            #pragma unroll
            for (int n8 = 0; n8 < 8; n8++) {
                const int n = wn + n8 * 8 + 2 * (lane & 3);
                float2 bw0 = bw2s[n];
                float2 bw1 = bw2s[n + 1];
                #pragma unroll
                for (int mb = 0; mb < 2; mb++) {
                    const float* c = C[mb][n8];
                    #pragma unroll
                    for (int h = 0; h < 2; h++) {
                        float y0 = c[2 * h]     + bw0.x;
                        float y1 = c[2 * h + 1] + bw1.x;
                        float ev0 = __expf(fminf(y0, 15.0f));
                        float ev1 = __expf(fminf(y1, 15.0f));
                        float p0 = 1.0f + ev0, p1 = 1.0f + ev1;
                        float p20 = p0 * p0,   p21 = p1 * p1;
                        float n0 = p20 - 1.0f, d0 = p20 + 1.0f;
                        float n1 = p21 - 1.0f, d1 = p21 + 1.0f;
                        float r = __fdividef(1.0f, d0 * d1);
                        float m0 = y0 * n0 * (d1 * r);
                        float m1 = y1 * n1 * (d0 * r);
                        psum[mb * 2 + h] = fmaf(bw0.y, m0, fmaf(bw1.y, m1, psum[mb * 2 + h]));
                    }
                }
            }
            #pragma unroll
            for (int q = 0; q < 4; q++) {
                psum[q] += __shfl_xor_sync(0xffffffffu, psum[q], 1);
                psum[q] += __shfl_xor_sync(0xffffffffu, psum[q], 2);
            }
            if ((lane & 3) == 0) {
                const int r = lane >> 2;    // 0..7
                #pragma unroll
                for (int mb = 0; mb < 2; mb++) {
                    part[(mb * 16 + r) * 4 + wg]     = psum[mb * 2 + 0];
                    part[(mb * 16 + r + 8) * 4 + wg] = psum[mb * 2 + 1];
                }
            }
        }
        GROUP_BAR(barid);   // part + next A ready (group scope only)

        if (gtid < TILE_M) {
            const int e = e_base + gtid;
            if (e < n_edges) {
                float4 p = *reinterpret_cast<const float4*>(part + gtid * 4);
                float s = (p.x + p.y) + (p.z + p.w) + bias2;
                out[e] = __fdividef(1.0f, 1.0f + __expf(-s));
            }
        }
    }
}

extern "C" void kernel_launch(void* const* d_in, const int* in_sizes, int n_in,
                              void* d_out, int out_size) {
    const float* zp  = (const float*)d_in[0];
    const void*  ep  = d_in[1];
    const float* W1p = (const float*)d_in[2];
    const float* b1p = (const float*)d_in[3];
    const float* W2p = (const float*)d_in[4];
    const float* b2p = (const float*)d_in[5];
    float* outp = (float*)d_out;
    const int n_edges = out_size;

    cudaFuncSetAttribute(edge_decoder_hmma,
                         cudaFuncAttributeMaxDynamicSharedMemorySize, SMEM_TOTAL);
    int sms = 148;
    cudaDeviceGetAttribute(&sms, cudaDevAttrMultiProcessorCount, 0);

    detect_edge_dtype<<<1, 32>>>((const unsigned int*)ep);
    edge_decoder_hmma<<<sms * 2, NTHREADS, SMEM_TOTAL>>>(
        zp, ep, W1p, b1p, W2p, b2p, outp, n_edges);
}